// round 15
// baseline (speedup 1.0000x reference)
#include <cuda_runtime.h>
#include <cuda_fp16.h>
#include <cstdint>

#define B_ 16
#define T_ 2048
#define J_ 128
#define D_ 1024

#define N_ATT1 (B_*T_*J_)
#define OFF_ATT2 N_ATT1
#define OFF_G (OFF_ATT2 + B_*T_)

#define TCH 32

// scores kernel smem map (bytes) — M=64, depth-2 (champion layout)
#define V_HH    0        // 2 x 8KB fp16 H tiles
#define V_UW    16384    // 3 x 16KB fp16 UW tiles
#define V_RED   65536    // 2KB
#define V_WS    67584    // 4KB (w1)
#define V_CTS   71680    // 512B
#define V_HROW  72192    // 256B
#define V_TOT   72448

#define SWZ8(r,c)  (((r)<<7) + (((c) ^ ((r)&7)) << 4))
#define SWZ16(r,c) (((r)<<8) + (((c) ^ ((r)&7)) << 4))

__device__ float g_ctp[B_*J_*32];     // colterm partials per 32-d chunk
__device__ float g_rowmax[B_*T_];
__device__ float g_agg2[B_*D_];
__device__ float g_agg2p[B_*TCH*D_];
__device__ __half g_uw3h[B_*J_*D_];   // fp16 U .* w3   [b][j][d]
__device__ __half g_uth[B_*D_*J_];    // fp16 U^T       [b][d][j]
__device__ __half g_att1h[B_*T_*J_];  // fp16 att1      [b][t][j]

__device__ __forceinline__ uint32_t smem_u32(const void* p){
    uint32_t a;
    asm("{ .reg .u64 t; cvta.to.shared.u64 t, %1; cvt.u32.u64 %0, t; }" : "=r"(a) : "l"(p));
    return a;
}
__device__ __forceinline__ void cp16(uint32_t s, const void* g){
    asm volatile("cp.async.cg.shared.global [%0], [%1], 16;" :: "r"(s), "l"(g));
}
#define CP_COMMIT asm volatile("cp.async.commit_group;")
#define CP_WAIT0  asm volatile("cp.async.wait_group 0;")
#define CP_WAIT1  asm volatile("cp.async.wait_group 1;")

__device__ __forceinline__ void ldm4(uint32_t r[4], uint32_t a){
    asm volatile("ldmatrix.sync.aligned.m8n8.x4.shared.b16 {%0,%1,%2,%3}, [%4];"
        : "=r"(r[0]), "=r"(r[1]), "=r"(r[2]), "=r"(r[3]) : "r"(a));
}
__device__ __forceinline__ void mma_f16(float c[4], const uint32_t a[4], uint32_t b0, uint32_t b1){
    asm volatile("mma.sync.aligned.m16n8k16.row.col.f32.f16.f16.f32 "
        "{%0,%1,%2,%3}, {%4,%5,%6,%7}, {%8,%9}, {%0,%1,%2,%3};"
        : "+f"(c[0]), "+f"(c[1]), "+f"(c[2]), "+f"(c[3])
        : "r"(a[0]), "r"(a[1]), "r"(a[2]), "r"(a[3]), "r"(b0), "r"(b1));
}

// -------- K0: merged prep — g_uw3h, g_uth, colterm partials --------
__global__ void uwt_kernel(const float* __restrict__ U, const float* __restrict__ w){
    __shared__ float t[32][33];
    __shared__ float w2s[32];
    int b = blockIdx.z, j0 = blockIdx.y*32, d0 = blockIdx.x*32;
    int tx = threadIdx.x, ty = threadIdx.y;   // 32 x 8
    float w3v = w[2*D_ + d0 + tx];
    if (ty == 0) w2s[tx] = w[D_ + d0 + tx];
    const float* Ub = U + ((size_t)b*J_ + j0)*D_ + d0;
    #pragma unroll
    for (int i = 0; i < 32; i += 8){
        float v = Ub[(size_t)(ty+i)*D_ + tx];
        t[ty+i][tx] = v;
        g_uw3h[((size_t)b*J_ + j0+ty+i)*D_ + d0 + tx] = __float2half(v * w3v);
    }
    __syncthreads();
    __half* Tb = g_uth + ((size_t)b*D_ + d0)*J_ + j0;
    #pragma unroll
    for (int i = 0; i < 32; i += 8) Tb[(size_t)(ty+i)*J_ + tx] = __float2half(t[tx][ty+i]);
    if (ty == 0){   // colterm partial for local j = tx over this 32-d chunk
        float s = 0.f;
        #pragma unroll
        for (int d = 0; d < 32; d++) s += t[tx][d] * w2s[d];
        g_ctp[((size_t)b*J_ + j0 + tx)*32 + (d0 >> 5)] = s;
    }
}

// -------- K1: scores + register softmax (M=64, depth-2 cp.async pipeline) --------
__global__ __launch_bounds__(256, 2)
void scores_kernel(const float* __restrict__ H, const float* __restrict__ w,
                   const float* __restrict__ bias, float* __restrict__ out){
    extern __shared__ char smc[];
    uint32_t smb = smem_u32(smc);
    float* red0 = (float*)(smc + V_RED);             // [64][4]
    float* red1 = red0 + 256;                        // [64][4]
    float* ws   = (float*)(smc + V_WS);
    float* cts  = (float*)(smc + V_CTS);
    float* hrow = (float*)(smc + V_HROW);

    int tid = threadIdx.x;
    int b = blockIdx.y, t0 = blockIdx.x * 64;
    int warp = tid >> 5, lane = tid & 31;
    int wm = warp >> 2, wn = warp & 3;
    int gid = lane >> 2, tig = lane & 3;
    int hr = tid >> 2, hq = tid & 3;

    const float*  Hb  = H + (size_t)(b*T_ + t0) * D_;
    const __half* UWb = g_uw3h + (size_t)b * J_ * D_;

    if (tid < 128){
        const float* p = g_ctp + ((size_t)b*J_ + tid)*32;
        float s = bias[0];
        #pragma unroll
        for (int c = 0; c < 32; c++) s += p[c];
        cts[tid] = s;
    }
    #pragma unroll
    for (int i = 0; i < 4; i++) ws[tid + i*256] = w[tid + i*256];

    // prologue: prefetch UW chunks 0 and 1 (two groups in flight)
    {
        int r = tid & 127, ch = tid >> 7;
        #pragma unroll
        for (int i = 0; i < 4; i++){
            int c16 = ch*4 + i;
            cp16(smb + V_UW + SWZ8(r, c16), UWb + (size_t)r*D_ + c16*8);
        }
        CP_COMMIT;
        #pragma unroll
        for (int i = 0; i < 4; i++){
            int c16 = ch*4 + i;
            cp16(smb + V_UW + 16384 + SWZ8(r, c16), UWb + (size_t)r*D_ + 64 + c16*8);
        }
        CP_COMMIT;
    }
    float4 hreg[4];
    #pragma unroll
    for (int i = 0; i < 4; i++)
        hreg[i] = *(const float4*)(Hb + (size_t)hr*D_ + (hq + 4*i)*4);
    __syncthreads();                                 // ws/cts visible

    float hp = 0.f;
    {   // STS H chunk0 (fp16) + hrow partial
        #pragma unroll
        for (int i = 0; i < 4; i++){
            int f4 = hq + 4*i;
            float4 h = hreg[i];
            __half2 p0 = __floats2half2_rn(h.x, h.y), p1 = __floats2half2_rn(h.z, h.w);
            uint32_t a = smb + V_HH + SWZ8(hr, f4 >> 1) + (f4 & 1)*8;
            asm volatile("st.shared.v2.b32 [%0], {%1,%2};" :: "r"(a),
                         "r"(*(uint32_t*)&p0), "r"(*(uint32_t*)&p1));
            int wb = hq*4 + 16*i;
            hp += h.x*ws[wb] + h.y*ws[wb+1] + h.z*ws[wb+2] + h.w*ws[wb+3];
        }
    }

    float acc[2][4][4];
    #pragma unroll
    for (int i = 0; i < 2; i++)
        #pragma unroll
        for (int j = 0; j < 4; j++)
            #pragma unroll
            for (int k = 0; k < 4; k++) acc[i][j][k] = 0.f;

    // ---- S = H @ (U.*w3)^T, K=1024 in 16 chunks of 64, UW pipeline depth 2 ----
    for (int kci = 0; kci < 16; kci++){
        if (kci < 15){
            #pragma unroll
            for (int i = 0; i < 4; i++)
                hreg[i] = *(const float4*)(Hb + (size_t)hr*D_ + (kci+1)*64 + (hq + 4*i)*4);
        }
        if (kci < 15){ CP_WAIT1; } else { CP_WAIT0; }
        __syncthreads();
        if (kci < 14){
            uint32_t ud = smb + V_UW + ((kci+2)%3)*16384;
            int r = tid & 127, ch = tid >> 7;
            #pragma unroll
            for (int i = 0; i < 4; i++){
                int c16 = ch*4 + i;
                cp16(ud + SWZ8(r, c16), UWb + (size_t)r*D_ + (kci+2)*64 + c16*8);
            }
            CP_COMMIT;
        }
        uint32_t bH = smb + V_HH + (kci & 1)*8192;
        uint32_t bUW = smb + V_UW + (kci % 3)*16384;
        int lrow = lane & 15;
        #pragma unroll
        for (int kt = 0; kt < 4; kt++){
            int lc16 = kt*2 + (lane >> 4);
            uint32_t af[2][4], bf[2][4];
            ldm4(af[0], bH  + SWZ8(wm*32      + lrow, lc16));
            ldm4(af[1], bH  + SWZ8(wm*32 + 16 + lrow, lc16));
            ldm4(bf[0], bUW + SWZ8(wn*32      + lrow, lc16));
            ldm4(bf[1], bUW + SWZ8(wn*32 + 16 + lrow, lc16));
            #pragma unroll
            for (int mt = 0; mt < 2; mt++)
                #pragma unroll
                for (int nt = 0; nt < 4; nt++)
                    mma_f16(acc[mt][nt], af[mt], bf[nt>>1][nt&1], bf[nt>>1][(nt&1)+2]);
        }
        if (kci < 15){
            uint32_t bH2 = smb + V_HH + ((kci+1) & 1)*8192;
            #pragma unroll
            for (int i = 0; i < 4; i++){
                int f4 = hq + 4*i;
                float4 h = hreg[i];
                __half2 p0 = __floats2half2_rn(h.x, h.y), p1 = __floats2half2_rn(h.z, h.w);
                uint32_t a = bH2 + SWZ8(hr, f4 >> 1) + (f4 & 1)*8;
                asm volatile("st.shared.v2.b32 [%0], {%1,%2};" :: "r"(a),
                             "r"(*(uint32_t*)&p0), "r"(*(uint32_t*)&p1));
                int wb = (kci+1)*64 + hq*4 + 16*i;
                hp += h.x*ws[wb] + h.y*ws[wb+1] + h.z*ws[wb+2] + h.w*ws[wb+3];
            }
        }
    }
    hp += __shfl_xor_sync(0xffffffffu, hp, 1);
    hp += __shfl_xor_sync(0xffffffffu, hp, 2);
    __syncthreads();
    if (hq == 0) hrow[hr] = hp;

    // ---- register softmax ----
    int col0 = wn*32 + 2*tig;           // + nt*8
    #pragma unroll
    for (int mt = 0; mt < 2; mt++)
        #pragma unroll
        for (int nt = 0; nt < 4; nt++){
            acc[mt][nt][0] += cts[col0 + nt*8];
            acc[mt][nt][1] += cts[col0 + nt*8 + 1];
            acc[mt][nt][2] += cts[col0 + nt*8];
            acc[mt][nt][3] += cts[col0 + nt*8 + 1];
        }
    float rm[2][2];
    #pragma unroll
    for (int mt = 0; mt < 2; mt++)
        #pragma unroll
        for (int h = 0; h < 2; h++){
            float m = fmaxf(acc[mt][0][2*h], acc[mt][0][2*h+1]);
            #pragma unroll
            for (int nt = 1; nt < 4; nt++)
                m = fmaxf(m, fmaxf(acc[mt][nt][2*h], acc[mt][nt][2*h+1]));
            m = fmaxf(m, __shfl_xor_sync(0xffffffffu, m, 1));
            m = fmaxf(m, __shfl_xor_sync(0xffffffffu, m, 2));
            rm[mt][h] = m;
        }
    if (tig == 0){
        #pragma unroll
        for (int mt = 0; mt < 2; mt++)
            #pragma unroll
            for (int h = 0; h < 2; h++)
                red0[(wm*32 + mt*16 + h*8 + gid)*4 + wn] = rm[mt][h];
    }
    __syncthreads();
    float rs[2][2];
    #pragma unroll
    for (int mt = 0; mt < 2; mt++)
        #pragma unroll
        for (int h = 0; h < 2; h++){
            int r = wm*32 + mt*16 + h*8 + gid;
            float m = fmaxf(fmaxf(red0[r*4], red0[r*4+1]), fmaxf(red0[r*4+2], red0[r*4+3]));
            rm[mt][h] = m;
            float s = 0.f;
            #pragma unroll
            for (int nt = 0; nt < 4; nt++){
                acc[mt][nt][2*h]   = __expf(acc[mt][nt][2*h]   - m);
                acc[mt][nt][2*h+1] = __expf(acc[mt][nt][2*h+1] - m);
                s += acc[mt][nt][2*h] + acc[mt][nt][2*h+1];
            }
            s += __shfl_xor_sync(0xffffffffu, s, 1);
            s += __shfl_xor_sync(0xffffffffu, s, 2);
            rs[mt][h] = s;
        }
    if (tig == 0){
        #pragma unroll
        for (int mt = 0; mt < 2; mt++)
            #pragma unroll
            for (int h = 0; h < 2; h++)
                red1[(wm*32 + mt*16 + h*8 + gid)*4 + wn] = rs[mt][h];
    }
    __syncthreads();
    float* att1out = out + (size_t)(b*T_ + t0) * J_;
    #pragma unroll
    for (int mt = 0; mt < 2; mt++)
        #pragma unroll
        for (int h = 0; h < 2; h++){
            int r = wm*32 + mt*16 + h*8 + gid;
            float inv = 1.f / (red1[r*4] + red1[r*4+1] + red1[r*4+2] + red1[r*4+3]);
            #pragma unroll
            for (int nt = 0; nt < 4; nt++){
                float e0 = acc[mt][nt][2*h] * inv;
                float e1 = acc[mt][nt][2*h+1] * inv;
                int c = col0 + nt*8;
                *(float2*)(att1out + (size_t)r*J_ + c) = make_float2(e0, e1);
                *(__half2*)(g_att1h + (size_t)(b*T_ + t0 + r)*J_ + c) = __floats2half2_rn(e0, e1);
            }
            if (wn == 0 && tig == 0)
                g_rowmax[b*T_ + t0 + r] = rm[mt][h] + hrow[r];
        }
}

// -------- K2: att2 = softmax_t(rowmax) --------
__global__ void att2_kernel(float* __restrict__ out){
    __shared__ float red[8];
    int b = blockIdx.x, tid = threadIdx.x;
    float v[8];
    #pragma unroll
    for (int i = 0; i < 8; i++) v[i] = g_rowmax[b*T_ + tid + i*256];
    float mx = v[0];
    #pragma unroll
    for (int i = 1; i < 8; i++) mx = fmaxf(mx, v[i]);
    #pragma unroll
    for (int o = 16; o; o >>= 1) mx = fmaxf(mx, __shfl_xor_sync(0xffffffffu, mx, o));
    if ((tid & 31) == 0) red[tid >> 5] = mx;
    __syncthreads();
    mx = red[0];
    #pragma unroll
    for (int i = 1; i < 8; i++) mx = fmaxf(mx, red[i]);
    float e[8], s = 0.f;
    #pragma unroll
    for (int i = 0; i < 8; i++){ e[i] = __expf(v[i] - mx); s += e[i]; }
    #pragma unroll
    for (int o = 16; o; o >>= 1) s += __shfl_xor_sync(0xffffffffu, s, o);
    __syncthreads();
    if ((tid & 31) == 0) red[tid >> 5] = s;
    __syncthreads();
    s = 0.f;
    #pragma unroll
    for (int i = 0; i < 8; i++) s += red[i];
    float inv = 1.f / s;
    #pragma unroll
    for (int i = 0; i < 8; i++) out[OFF_ATT2 + b*T_ + tid + i*256] = e[i] * inv;
}

// -------- K3a: partial agg2 --------
__global__ __launch_bounds__(128)
void agg2p_kernel(const float* __restrict__ H, const float* __restrict__ out){
    int b  = blockIdx.z;
    int tc = blockIdx.y;
    int d4 = blockIdx.x * 128 + threadIdx.x;
    int t0 = tc * (T_/TCH);
    const float* a2 = out + OFF_ATT2 + b*T_ + t0;
    const float4* Hb = (const float4*)(H + ((size_t)b*T_ + t0) * D_) + d4;
    float4 acc = make_float4(0.f, 0.f, 0.f, 0.f);
    #pragma unroll 1
    for (int t = 0; t < T_/TCH; t += 8){
        #pragma unroll
        for (int u = 0; u < 8; u++){
            float a = a2[t+u];
            float4 h = Hb[(size_t)(t+u) * 256];
            acc.x += a*h.x; acc.y += a*h.y; acc.z += a*h.z; acc.w += a*h.w;
        }
    }
    ((float4*)g_agg2p)[((size_t)b*TCH + tc)*256 + d4] = acc;
}

// -------- K3b: reduce --------
__global__ void agg2r_kernel(){
    int idx = blockIdx.x * 256 + threadIdx.x;
    int b = idx >> 10, d = idx & 1023;
    const float* p = g_agg2p + (size_t)b*TCH*D_ + d;
    float acc = 0.f;
    #pragma unroll
    for (int c = 0; c < TCH; c++) acc += p[(size_t)c*D_];
    g_agg2[idx] = acc;
}

// -------- K1b: agg1 = att1 @ U + full G epilogue (G1..G4) --------
__global__ __launch_bounds__(256, 3)
void agg1g_kernel(const float* __restrict__ H, float* __restrict__ out){
    extern __shared__ char smc[];
    uint32_t smb = smem_u32(smc);
    float* stage = (float*)smc;      // 128 x 68 fp32, overlays A/B after mma
    int tid = threadIdx.x;
    int b  = blockIdx.z;
    int m0 = blockIdx.y * 128;       // t rows
    int n0 = blockIdx.x * 64;        // d cols
    int warp = tid >> 5, lane = tid & 31;
    int wm = warp >> 1, wn = warp & 1;
    int gid = lane >> 2, tig = lane & 3;

    const __half* Ab = g_att1h + (size_t)(b*T_ + m0) * J_;
    const __half* Bb = g_uth + ((size_t)b*D_ + n0) * J_;

    #pragma unroll
    for (int i = 0; i < 8; i++){
        int idx = tid + i*256;       // < 2048
        int r = idx >> 4, c = idx & 15;
        cp16(smb + SWZ16(r, c), Ab + (size_t)r*J_ + c*8);
    }
    #pragma unroll
    for (int i = 0; i < 4; i++){
        int idx = tid + i*256;       // < 1024
        int r = idx >> 4, c = idx & 15;
        cp16(smb + 32768 + SWZ16(r, c), Bb + (size_t)r*J_ + c*8);
    }
    CP_COMMIT;

    float acc[2][4][4];
    #pragma unroll
    for (int i = 0; i < 2; i++)
        #pragma unroll
        for (int j = 0; j < 4; j++)
            #pragma unroll
            for (int k = 0; k < 4; k++) acc[i][j][k] = 0.f;

    CP_WAIT0;
    __syncthreads();

    int lrow = lane & 15;
    uint32_t aB = smb, bB = smb + 32768;
    #pragma unroll
    for (int kt = 0; kt < 8; kt++){
        int lc16 = kt*2 + (lane >> 4);
        uint32_t af[2][4], bf[2][4];
        ldm4(af[0], aB + SWZ16(wm*32      + lrow, lc16));
        ldm4(af[1], aB + SWZ16(wm*32 + 16 + lrow, lc16));
        ldm4(bf[0], bB + SWZ16(wn*32      + lrow, lc16));
        ldm4(bf[1], bB + SWZ16(wn*32 + 16 + lrow, lc16));
        #pragma unroll
        for (int mt = 0; mt < 2; mt++)
            #pragma unroll
            for (int nt = 0; nt < 4; nt++)
                mma_f16(acc[mt][nt], af[mt], bf[nt>>1][nt&1], bf[nt>>1][(nt&1)+2]);
    }
    __syncthreads();

    #pragma unroll
    for (int mt = 0; mt < 2; mt++)
        #pragma unroll
        for (int nt = 0; nt < 4; nt++){
            int r0 = wm*32 + mt*16 + gid;
            int c  = wn*32 + nt*8 + 2*tig;
            *(float2*)(stage + r0*68 + c)     = make_float2(acc[mt][nt][0], acc[mt][nt][1]);
            *(float2*)(stage + (r0+8)*68 + c) = make_float2(acc[mt][nt][2], acc[mt][nt][3]);
        }
    __syncthreads();

    const float* Hb = H + (size_t)(b*T_ + m0) * D_ + n0;
    const float* A2 = g_agg2 + b*D_ + n0;
    float* Gb = out + OFF_G + (size_t)(b*T_ + m0) * 4096 + n0;
    #pragma unroll
    for (int it = 0; it < 8; it++){
        int idx = tid + it*256;       // < 2048
        int r = idx >> 4, c4 = (idx & 15)*4;
        float4 a1 = *(float4*)(stage + r*68 + c4);
        float4 h  = *(const float4*)(Hb + (size_t)r*D_ + c4);
        float4 a2 = *(const float4*)(A2 + c4);
        float* g = Gb + (size_t)r*4096 + c4;
        *(float4*)(g)        = h;
        *(float4*)(g + 1024) = a1;
        *(float4*)(g + 2048) = make_float4(a1.x*h.x, a1.y*h.y, a1.z*h.z, a1.w*h.w);
        *(float4*)(g + 3072) = make_float4(h.x*a2.x, h.y*a2.y, h.z*a2.z, h.w*a2.w);
    }
}

extern "C" void kernel_launch(void* const* d_in, const int* in_sizes, int n_in,
                              void* d_out, int out_size){
    const float* H    = (const float*)d_in[0];
    const float* U    = (const float*)d_in[1];
    const float* w    = (const float*)d_in[2];
    const float* bias = (const float*)d_in[3];
    float* out = (float*)d_out;

    cudaFuncSetAttribute(scores_kernel, cudaFuncAttributeMaxDynamicSharedMemorySize, V_TOT);
    cudaFuncSetAttribute(agg1g_kernel, cudaFuncAttributeMaxDynamicSharedMemorySize, 49152);

    uwt_kernel<<<dim3(D_/32, J_/32, B_), dim3(32, 8)>>>(U, w);
    scores_kernel<<<dim3(T_/64, B_), 256, V_TOT>>>(H, w, bias, out);
    att2_kernel<<<B_, 256>>>(out);
    agg2p_kernel<<<dim3(2, TCH, B_), 128>>>(H, out);
    agg2r_kernel<<<B_*D_/256, 256>>>();
    agg1g_kernel<<<dim3(D_/64, T_/128, B_), 256, 49152>>>(H, out);
}

// round 16
// speedup vs baseline: 1.0118x; 1.0118x over previous
#include <cuda_runtime.h>
#include <cuda_fp16.h>
#include <cstdint>

#define B_ 16
#define T_ 2048
#define J_ 128
#define D_ 1024

#define N_ATT1 (B_*T_*J_)
#define OFF_ATT2 N_ATT1
#define OFF_G (OFF_ATT2 + B_*T_)

#define TCH 64

// scores kernel smem map (bytes) — M=64, depth-2 (champion layout)
#define V_HH    0        // 2 x 8KB fp16 H tiles
#define V_UW    16384    // 3 x 16KB fp16 UW tiles
#define V_RED   65536    // 2KB
#define V_WS    67584    // 4KB (w1)
#define V_CTS   71680    // 512B
#define V_HROW  72192    // 256B
#define V_TOT   72448

#define SWZ8(r,c)  (((r)<<7) + (((c) ^ ((r)&7)) << 4))
#define SWZ16(r,c) (((r)<<8) + (((c) ^ ((r)&7)) << 4))

__device__ float g_colterm[B_*J_];
__device__ float g_rowmax[B_*T_];
__device__ float g_agg2[B_*D_];
__device__ float g_agg2p[B_*TCH*D_];
__device__ __half g_uw3h[B_*J_*D_];   // fp16 U .* w3   [b][j][d]
__device__ __half g_uth[B_*D_*J_];    // fp16 U^T       [b][d][j]
__device__ __half g_att1h[B_*T_*J_];  // fp16 att1      [b][t][j]

__device__ __forceinline__ uint32_t smem_u32(const void* p){
    uint32_t a;
    asm("{ .reg .u64 t; cvta.to.shared.u64 t, %1; cvt.u32.u64 %0, t; }" : "=r"(a) : "l"(p));
    return a;
}
__device__ __forceinline__ void cp16(uint32_t s, const void* g){
    asm volatile("cp.async.cg.shared.global [%0], [%1], 16;" :: "r"(s), "l"(g));
}
#define CP_COMMIT asm volatile("cp.async.commit_group;")
#define CP_WAIT0  asm volatile("cp.async.wait_group 0;")
#define CP_WAIT1  asm volatile("cp.async.wait_group 1;")

__device__ __forceinline__ void ldm4(uint32_t r[4], uint32_t a){
    asm volatile("ldmatrix.sync.aligned.m8n8.x4.shared.b16 {%0,%1,%2,%3}, [%4];"
        : "=r"(r[0]), "=r"(r[1]), "=r"(r[2]), "=r"(r[3]) : "r"(a));
}
__device__ __forceinline__ void mma_f16(float c[4], const uint32_t a[4], uint32_t b0, uint32_t b1){
    asm volatile("mma.sync.aligned.m16n8k16.row.col.f32.f16.f16.f32 "
        "{%0,%1,%2,%3}, {%4,%5,%6,%7}, {%8,%9}, {%0,%1,%2,%3};"
        : "+f"(c[0]), "+f"(c[1]), "+f"(c[2]), "+f"(c[3])
        : "r"(a[0]), "r"(a[1]), "r"(a[2]), "r"(a[3]), "r"(b0), "r"(b1));
}

// -------- K0a: colterm --------
__global__ void colterm_kernel(const float* __restrict__ U, const float* __restrict__ w,
                               const float* __restrict__ bias){
    int pair = blockIdx.x * 8 + (threadIdx.x >> 5);
    int lane = threadIdx.x & 31;
    const float* u  = U + (size_t)pair * D_;
    const float* w2 = w + D_;
    float s = 0.f;
    for (int k = lane; k < D_; k += 32) s += u[k] * w2[k];
    #pragma unroll
    for (int o = 16; o; o >>= 1) s += __shfl_xor_sync(0xffffffffu, s, o);
    if (lane == 0) g_colterm[pair] = s + bias[0];
}

// -------- K0b: merged prep — g_uw3h = fp16(U.*w3), g_uth = fp16(U^T) --------
__global__ void uwt_kernel(const float* __restrict__ U, const float* __restrict__ w){
    __shared__ float t[32][33];
    int b = blockIdx.z, j0 = blockIdx.y*32, d0 = blockIdx.x*32;
    int tx = threadIdx.x, ty = threadIdx.y;   // 32 x 8
    float w3v = w[2*D_ + d0 + tx];
    const float* Ub = U + ((size_t)b*J_ + j0)*D_ + d0;
    #pragma unroll
    for (int i = 0; i < 32; i += 8){
        float v = Ub[(size_t)(ty+i)*D_ + tx];
        t[ty+i][tx] = v;
        g_uw3h[((size_t)b*J_ + j0+ty+i)*D_ + d0 + tx] = __float2half(v * w3v);
    }
    __syncthreads();
    __half* Tb = g_uth + ((size_t)b*D_ + d0)*J_ + j0;
    #pragma unroll
    for (int i = 0; i < 32; i += 8) Tb[(size_t)(ty+i)*J_ + tx] = __float2half(t[tx][ty+i]);
}

// -------- K1: scores + register softmax (M=64, depth-2 cp.async pipeline) --------
__global__ __launch_bounds__(256, 2)
void scores_kernel(const float* __restrict__ H, const float* __restrict__ w,
                   float* __restrict__ out){
    extern __shared__ char smc[];
    uint32_t smb = smem_u32(smc);
    float* red0 = (float*)(smc + V_RED);             // [64][4]
    float* red1 = red0 + 256;                        // [64][4]
    float* ws   = (float*)(smc + V_WS);
    float* cts  = (float*)(smc + V_CTS);
    float* hrow = (float*)(smc + V_HROW);

    int tid = threadIdx.x;
    int b = blockIdx.y, t0 = blockIdx.x * 64;
    int warp = tid >> 5, lane = tid & 31;
    int wm = warp >> 2, wn = warp & 3;
    int gid = lane >> 2, tig = lane & 3;
    int hr = tid >> 2, hq = tid & 3;

    const float*  Hb  = H + (size_t)(b*T_ + t0) * D_;
    const __half* UWb = g_uw3h + (size_t)b * J_ * D_;

    if (tid < 128) cts[tid] = g_colterm[b*J_ + tid];
    #pragma unroll
    for (int i = 0; i < 4; i++) ws[tid + i*256] = w[tid + i*256];

    // prologue: prefetch UW chunks 0 and 1 (two groups in flight)
    {
        int r = tid & 127, ch = tid >> 7;
        #pragma unroll
        for (int i = 0; i < 4; i++){
            int c16 = ch*4 + i;
            cp16(smb + V_UW + SWZ8(r, c16), UWb + (size_t)r*D_ + c16*8);
        }
        CP_COMMIT;
        #pragma unroll
        for (int i = 0; i < 4; i++){
            int c16 = ch*4 + i;
            cp16(smb + V_UW + 16384 + SWZ8(r, c16), UWb + (size_t)r*D_ + 64 + c16*8);
        }
        CP_COMMIT;
    }
    float4 hreg[4];
    #pragma unroll
    for (int i = 0; i < 4; i++)
        hreg[i] = *(const float4*)(Hb + (size_t)hr*D_ + (hq + 4*i)*4);
    __syncthreads();                                 // ws/cts visible

    float hp = 0.f;
    {   // STS H chunk0 (fp16) + hrow partial
        #pragma unroll
        for (int i = 0; i < 4; i++){
            int f4 = hq + 4*i;
            float4 h = hreg[i];
            __half2 p0 = __floats2half2_rn(h.x, h.y), p1 = __floats2half2_rn(h.z, h.w);
            uint32_t a = smb + V_HH + SWZ8(hr, f4 >> 1) + (f4 & 1)*8;
            asm volatile("st.shared.v2.b32 [%0], {%1,%2};" :: "r"(a),
                         "r"(*(uint32_t*)&p0), "r"(*(uint32_t*)&p1));
            int wb = hq*4 + 16*i;
            hp += h.x*ws[wb] + h.y*ws[wb+1] + h.z*ws[wb+2] + h.w*ws[wb+3];
        }
    }

    float acc[2][4][4];
    #pragma unroll
    for (int i = 0; i < 2; i++)
        #pragma unroll
        for (int j = 0; j < 4; j++)
            #pragma unroll
            for (int k = 0; k < 4; k++) acc[i][j][k] = 0.f;

    // ---- S = H @ (U.*w3)^T, K=1024 in 16 chunks of 64, UW pipeline depth 2 ----
    for (int kci = 0; kci < 16; kci++){
        if (kci < 15){
            #pragma unroll
            for (int i = 0; i < 4; i++)
                hreg[i] = *(const float4*)(Hb + (size_t)hr*D_ + (kci+1)*64 + (hq + 4*i)*4);
        }
        if (kci < 15){ CP_WAIT1; } else { CP_WAIT0; }
        __syncthreads();
        if (kci < 14){
            uint32_t ud = smb + V_UW + ((kci+2)%3)*16384;
            int r = tid & 127, ch = tid >> 7;
            #pragma unroll
            for (int i = 0; i < 4; i++){
                int c16 = ch*4 + i;
                cp16(ud + SWZ8(r, c16), UWb + (size_t)r*D_ + (kci+2)*64 + c16*8);
            }
            CP_COMMIT;
        }
        uint32_t bH = smb + V_HH + (kci & 1)*8192;
        uint32_t bUW = smb + V_UW + (kci % 3)*16384;
        int lrow = lane & 15;
        #pragma unroll
        for (int kt = 0; kt < 4; kt++){
            int lc16 = kt*2 + (lane >> 4);
            uint32_t af[2][4], bf[2][4];
            ldm4(af[0], bH  + SWZ8(wm*32      + lrow, lc16));
            ldm4(af[1], bH  + SWZ8(wm*32 + 16 + lrow, lc16));
            ldm4(bf[0], bUW + SWZ8(wn*32      + lrow, lc16));
            ldm4(bf[1], bUW + SWZ8(wn*32 + 16 + lrow, lc16));
            #pragma unroll
            for (int mt = 0; mt < 2; mt++)
                #pragma unroll
                for (int nt = 0; nt < 4; nt++)
                    mma_f16(acc[mt][nt], af[mt], bf[nt>>1][nt&1], bf[nt>>1][(nt&1)+2]);
        }
        if (kci < 15){
            uint32_t bH2 = smb + V_HH + ((kci+1) & 1)*8192;
            #pragma unroll
            for (int i = 0; i < 4; i++){
                int f4 = hq + 4*i;
                float4 h = hreg[i];
                __half2 p0 = __floats2half2_rn(h.x, h.y), p1 = __floats2half2_rn(h.z, h.w);
                uint32_t a = bH2 + SWZ8(hr, f4 >> 1) + (f4 & 1)*8;
                asm volatile("st.shared.v2.b32 [%0], {%1,%2};" :: "r"(a),
                             "r"(*(uint32_t*)&p0), "r"(*(uint32_t*)&p1));
                int wb = (kci+1)*64 + hq*4 + 16*i;
                hp += h.x*ws[wb] + h.y*ws[wb+1] + h.z*ws[wb+2] + h.w*ws[wb+3];
            }
        }
    }
    hp += __shfl_xor_sync(0xffffffffu, hp, 1);
    hp += __shfl_xor_sync(0xffffffffu, hp, 2);
    __syncthreads();
    if (hq == 0) hrow[hr] = hp;

    // ---- register softmax ----
    int col0 = wn*32 + 2*tig;           // + nt*8
    #pragma unroll
    for (int mt = 0; mt < 2; mt++)
        #pragma unroll
        for (int nt = 0; nt < 4; nt++){
            acc[mt][nt][0] += cts[col0 + nt*8];
            acc[mt][nt][1] += cts[col0 + nt*8 + 1];
            acc[mt][nt][2] += cts[col0 + nt*8];
            acc[mt][nt][3] += cts[col0 + nt*8 + 1];
        }
    float rm[2][2];
    #pragma unroll
    for (int mt = 0; mt < 2; mt++)
        #pragma unroll
        for (int h = 0; h < 2; h++){
            float m = fmaxf(acc[mt][0][2*h], acc[mt][0][2*h+1]);
            #pragma unroll
            for (int nt = 1; nt < 4; nt++)
                m = fmaxf(m, fmaxf(acc[mt][nt][2*h], acc[mt][nt][2*h+1]));
            m = fmaxf(m, __shfl_xor_sync(0xffffffffu, m, 1));
            m = fmaxf(m, __shfl_xor_sync(0xffffffffu, m, 2));
            rm[mt][h] = m;
        }
    if (tig == 0){
        #pragma unroll
        for (int mt = 0; mt < 2; mt++)
            #pragma unroll
            for (int h = 0; h < 2; h++)
                red0[(wm*32 + mt*16 + h*8 + gid)*4 + wn] = rm[mt][h];
    }
    __syncthreads();
    float rs[2][2];
    #pragma unroll
    for (int mt = 0; mt < 2; mt++)
        #pragma unroll
        for (int h = 0; h < 2; h++){
            int r = wm*32 + mt*16 + h*8 + gid;
            float m = fmaxf(fmaxf(red0[r*4], red0[r*4+1]), fmaxf(red0[r*4+2], red0[r*4+3]));
            rm[mt][h] = m;
            float s = 0.f;
            #pragma unroll
            for (int nt = 0; nt < 4; nt++){
                acc[mt][nt][2*h]   = __expf(acc[mt][nt][2*h]   - m);
                acc[mt][nt][2*h+1] = __expf(acc[mt][nt][2*h+1] - m);
                s += acc[mt][nt][2*h] + acc[mt][nt][2*h+1];
            }
            s += __shfl_xor_sync(0xffffffffu, s, 1);
            s += __shfl_xor_sync(0xffffffffu, s, 2);
            rs[mt][h] = s;
        }
    if (tig == 0){
        #pragma unroll
        for (int mt = 0; mt < 2; mt++)
            #pragma unroll
            for (int h = 0; h < 2; h++)
                red1[(wm*32 + mt*16 + h*8 + gid)*4 + wn] = rs[mt][h];
    }
    __syncthreads();
    float* att1out = out + (size_t)(b*T_ + t0) * J_;
    #pragma unroll
    for (int mt = 0; mt < 2; mt++)
        #pragma unroll
        for (int h = 0; h < 2; h++){
            int r = wm*32 + mt*16 + h*8 + gid;
            float inv = 1.f / (red1[r*4] + red1[r*4+1] + red1[r*4+2] + red1[r*4+3]);
            #pragma unroll
            for (int nt = 0; nt < 4; nt++){
                float e0 = acc[mt][nt][2*h] * inv;
                float e1 = acc[mt][nt][2*h+1] * inv;
                int c = col0 + nt*8;
                *(float2*)(att1out + (size_t)r*J_ + c) = make_float2(e0, e1);
                *(__half2*)(g_att1h + (size_t)(b*T_ + t0 + r)*J_ + c) = __floats2half2_rn(e0, e1);
            }
            if (wn == 0 && tig == 0)
                g_rowmax[b*T_ + t0 + r] = rm[mt][h] + hrow[r];
        }
}

// -------- K2: att2 = softmax_t(rowmax) --------
__global__ void att2_kernel(float* __restrict__ out){
    __shared__ float red[8];
    int b = blockIdx.x, tid = threadIdx.x;
    float v[8];
    #pragma unroll
    for (int i = 0; i < 8; i++) v[i] = g_rowmax[b*T_ + tid + i*256];
    float mx = v[0];
    #pragma unroll
    for (int i = 1; i < 8; i++) mx = fmaxf(mx, v[i]);
    #pragma unroll
    for (int o = 16; o; o >>= 1) mx = fmaxf(mx, __shfl_xor_sync(0xffffffffu, mx, o));
    if ((tid & 31) == 0) red[tid >> 5] = mx;
    __syncthreads();
    mx = red[0];
    #pragma unroll
    for (int i = 1; i < 8; i++) mx = fmaxf(mx, red[i]);
    float e[8], s = 0.f;
    #pragma unroll
    for (int i = 0; i < 8; i++){ e[i] = __expf(v[i] - mx); s += e[i]; }
    #pragma unroll
    for (int o = 16; o; o >>= 1) s += __shfl_xor_sync(0xffffffffu, s, o);
    __syncthreads();
    if ((tid & 31) == 0) red[tid >> 5] = s;
    __syncthreads();
    s = 0.f;
    #pragma unroll
    for (int i = 0; i < 8; i++) s += red[i];
    float inv = 1.f / s;
    #pragma unroll
    for (int i = 0; i < 8; i++) out[OFF_ATT2 + b*T_ + tid + i*256] = e[i] * inv;
}

// -------- K3a: partial agg2 (TCH=64 -> grid 2048, ~14 CTA/SM) --------
__global__ __launch_bounds__(128)
void agg2p_kernel(const float* __restrict__ H, const float* __restrict__ out){
    int b  = blockIdx.z;
    int tc = blockIdx.y;
    int d4 = blockIdx.x * 128 + threadIdx.x;
    int t0 = tc * (T_/TCH);
    const float* a2 = out + OFF_ATT2 + b*T_ + t0;
    const float4* Hb = (const float4*)(H + ((size_t)b*T_ + t0) * D_) + d4;
    float4 acc = make_float4(0.f, 0.f, 0.f, 0.f);
    #pragma unroll 1
    for (int t = 0; t < T_/TCH; t += 8){
        #pragma unroll
        for (int u = 0; u < 8; u++){
            float a = a2[t+u];
            float4 h = Hb[(size_t)(t+u) * 256];
            acc.x += a*h.x; acc.y += a*h.y; acc.z += a*h.z; acc.w += a*h.w;
        }
    }
    ((float4*)g_agg2p)[((size_t)b*TCH + tc)*256 + d4] = acc;
}

// -------- K3b: reduce --------
__global__ void agg2r_kernel(){
    int idx = blockIdx.x * 256 + threadIdx.x;
    int b = idx >> 10, d = idx & 1023;
    const float* p = g_agg2p + (size_t)b*TCH*D_ + d;
    float acc = 0.f;
    #pragma unroll
    for (int c = 0; c < TCH; c++) acc += p[(size_t)c*D_];
    g_agg2[idx] = acc;
}

// -------- K1b: agg1 = att1 @ U + full G epilogue (G1..G4) --------
__global__ __launch_bounds__(256, 3)
void agg1g_kernel(const float* __restrict__ H, float* __restrict__ out){
    extern __shared__ char smc[];
    uint32_t smb = smem_u32(smc);
    float* stage = (float*)smc;      // 128 x 68 fp32, overlays A/B after mma
    int tid = threadIdx.x;
    int b  = blockIdx.z;
    int m0 = blockIdx.y * 128;       // t rows
    int n0 = blockIdx.x * 64;        // d cols
    int warp = tid >> 5, lane = tid & 31;
    int wm = warp >> 1, wn = warp & 1;
    int gid = lane >> 2, tig = lane & 3;

    const __half* Ab = g_att1h + (size_t)(b*T_ + m0) * J_;
    const __half* Bb = g_uth + ((size_t)b*D_ + n0) * J_;

    #pragma unroll
    for (int i = 0; i < 8; i++){
        int idx = tid + i*256;       // < 2048
        int r = idx >> 4, c = idx & 15;
        cp16(smb + SWZ16(r, c), Ab + (size_t)r*J_ + c*8);
    }
    #pragma unroll
    for (int i = 0; i < 4; i++){
        int idx = tid + i*256;       // < 1024
        int r = idx >> 4, c = idx & 15;
        cp16(smb + 32768 + SWZ16(r, c), Bb + (size_t)r*J_ + c*8);
    }
    CP_COMMIT;

    float acc[2][4][4];
    #pragma unroll
    for (int i = 0; i < 2; i++)
        #pragma unroll
        for (int j = 0; j < 4; j++)
            #pragma unroll
            for (int k = 0; k < 4; k++) acc[i][j][k] = 0.f;

    CP_WAIT0;
    __syncthreads();

    int lrow = lane & 15;
    uint32_t aB = smb, bB = smb + 32768;
    #pragma unroll
    for (int kt = 0; kt < 8; kt++){
        int lc16 = kt*2 + (lane >> 4);
        uint32_t af[2][4], bf[2][4];
        ldm4(af[0], aB + SWZ16(wm*32      + lrow, lc16));
        ldm4(af[1], aB + SWZ16(wm*32 + 16 + lrow, lc16));
        ldm4(bf[0], bB + SWZ16(wn*32      + lrow, lc16));
        ldm4(bf[1], bB + SWZ16(wn*32 + 16 + lrow, lc16));
        #pragma unroll
        for (int mt = 0; mt < 2; mt++)
            #pragma unroll
            for (int nt = 0; nt < 4; nt++)
                mma_f16(acc[mt][nt], af[mt], bf[nt>>1][nt&1], bf[nt>>1][(nt&1)+2]);
    }
    __syncthreads();

    #pragma unroll
    for (int mt = 0; mt < 2; mt++)
        #pragma unroll
        for (int nt = 0; nt < 4; nt++){
            int r0 = wm*32 + mt*16 + gid;
            int c  = wn*32 + nt*8 + 2*tig;
            *(float2*)(stage + r0*68 + c)     = make_float2(acc[mt][nt][0], acc[mt][nt][1]);
            *(float2*)(stage + (r0+8)*68 + c) = make_float2(acc[mt][nt][2], acc[mt][nt][3]);
        }
    __syncthreads();

    const float* Hb = H + (size_t)(b*T_ + m0) * D_ + n0;
    const float* A2 = g_agg2 + b*D_ + n0;
    float* Gb = out + OFF_G + (size_t)(b*T_ + m0) * 4096 + n0;
    #pragma unroll
    for (int it = 0; it < 8; it++){
        int idx = tid + it*256;       // < 2048
        int r = idx >> 4, c4 = (idx & 15)*4;
        float4 a1 = *(float4*)(stage + r*68 + c4);
        float4 h  = *(const float4*)(Hb + (size_t)r*D_ + c4);
        float4 a2 = *(const float4*)(A2 + c4);
        float* g = Gb + (size_t)r*4096 + c4;
        *(float4*)(g)        = h;
        *(float4*)(g + 1024) = a1;
        *(float4*)(g + 2048) = make_float4(a1.x*h.x, a1.y*h.y, a1.z*h.z, a1.w*h.w);
        *(float4*)(g + 3072) = make_float4(h.x*a2.x, h.y*a2.y, h.z*a2.z, h.w*a2.w);
    }
}

extern "C" void kernel_launch(void* const* d_in, const int* in_sizes, int n_in,
                              void* d_out, int out_size){
    const float* H    = (const float*)d_in[0];
    const float* U    = (const float*)d_in[1];
    const float* w    = (const float*)d_in[2];
    const float* bias = (const float*)d_in[3];
    float* out = (float*)d_out;

    cudaFuncSetAttribute(scores_kernel, cudaFuncAttributeMaxDynamicSharedMemorySize, V_TOT);
    cudaFuncSetAttribute(agg1g_kernel, cudaFuncAttributeMaxDynamicSharedMemorySize, 49152);

    colterm_kernel<<<256, 256>>>(U, w, bias);
    uwt_kernel<<<dim3(D_/32, J_/32, B_), dim3(32, 8)>>>(U, w);
    scores_kernel<<<dim3(T_/64, B_), 256, V_TOT>>>(H, w, out);
    att2_kernel<<<B_, 256>>>(out);
    agg2p_kernel<<<dim3(2, TCH, B_), 128>>>(H, out);
    agg2r_kernel<<<B_*D_/256, 256>>>();
    agg1g_kernel<<<dim3(D_/64, T_/128, B_), 256, 49152>>>(H, out);
}

// round 17
// speedup vs baseline: 1.0223x; 1.0104x over previous
#include <cuda_runtime.h>
#include <cuda_fp16.h>
#include <cstdint>

#define B_ 16
#define T_ 2048
#define J_ 128
#define D_ 1024

#define N_ATT1 (B_*T_*J_)
#define OFF_ATT2 N_ATT1
#define OFF_G (OFF_ATT2 + B_*T_)

#define TCH 64

// scores kernel smem map (bytes) — M=64, depth-2 (champion layout)
#define V_HH    0        // 2 x 8KB fp16 H tiles
#define V_UW    16384    // 3 x 16KB fp16 UW tiles; reused as att1 stage post-mainloop
#define V_RED   65536    // 2KB
#define V_WS    67584    // 4KB (w1)
#define V_CTS   71680    // 512B
#define V_HROW  72192    // 256B
#define V_TOT   72448

#define SWZ8(r,c)  (((r)<<7) + (((c) ^ ((r)&7)) << 4))
#define SWZ16(r,c) (((r)<<8) + (((c) ^ ((r)&7)) << 4))

__device__ float g_colterm[B_*J_];
__device__ float g_rowmax[B_*T_];
__device__ float g_agg2[B_*D_];
__device__ float g_agg2p[B_*TCH*D_];
__device__ __half g_uw3h[B_*J_*D_];   // fp16 U .* w3   [b][j][d]
__device__ __half g_uth[B_*D_*J_];    // fp16 U^T       [b][d][j]
__device__ __half g_att1h[B_*T_*J_];  // fp16 att1      [b][t][j]

__device__ __forceinline__ uint32_t smem_u32(const void* p){
    uint32_t a;
    asm("{ .reg .u64 t; cvta.to.shared.u64 t, %1; cvt.u32.u64 %0, t; }" : "=r"(a) : "l"(p));
    return a;
}
__device__ __forceinline__ void cp16(uint32_t s, const void* g){
    asm volatile("cp.async.cg.shared.global [%0], [%1], 16;" :: "r"(s), "l"(g));
}
#define CP_COMMIT asm volatile("cp.async.commit_group;")
#define CP_WAIT0  asm volatile("cp.async.wait_group 0;")
#define CP_WAIT1  asm volatile("cp.async.wait_group 1;")

__device__ __forceinline__ void ldm4(uint32_t r[4], uint32_t a){
    asm volatile("ldmatrix.sync.aligned.m8n8.x4.shared.b16 {%0,%1,%2,%3}, [%4];"
        : "=r"(r[0]), "=r"(r[1]), "=r"(r[2]), "=r"(r[3]) : "r"(a));
}
__device__ __forceinline__ void mma_f16(float c[4], const uint32_t a[4], uint32_t b0, uint32_t b1){
    asm volatile("mma.sync.aligned.m16n8k16.row.col.f32.f16.f16.f32 "
        "{%0,%1,%2,%3}, {%4,%5,%6,%7}, {%8,%9}, {%0,%1,%2,%3};"
        : "+f"(c[0]), "+f"(c[1]), "+f"(c[2]), "+f"(c[3])
        : "r"(a[0]), "r"(a[1]), "r"(a[2]), "r"(a[3]), "r"(b0), "r"(b1));
}

// -------- K0a: colterm --------
__global__ void colterm_kernel(const float* __restrict__ U, const float* __restrict__ w,
                               const float* __restrict__ bias){
    int pair = blockIdx.x * 8 + (threadIdx.x >> 5);
    int lane = threadIdx.x & 31;
    const float* u  = U + (size_t)pair * D_;
    const float* w2 = w + D_;
    float s = 0.f;
    for (int k = lane; k < D_; k += 32) s += u[k] * w2[k];
    #pragma unroll
    for (int o = 16; o; o >>= 1) s += __shfl_xor_sync(0xffffffffu, s, o);
    if (lane == 0) g_colterm[pair] = s + bias[0];
}

// -------- K0b: merged prep — g_uw3h = fp16(U.*w3), g_uth = fp16(U^T) --------
__global__ void uwt_kernel(const float* __restrict__ U, const float* __restrict__ w){
    __shared__ float t[32][33];
    int b = blockIdx.z, j0 = blockIdx.y*32, d0 = blockIdx.x*32;
    int tx = threadIdx.x, ty = threadIdx.y;   // 32 x 8
    float w3v = w[2*D_ + d0 + tx];
    const float* Ub = U + ((size_t)b*J_ + j0)*D_ + d0;
    #pragma unroll
    for (int i = 0; i < 32; i += 8){
        float v = Ub[(size_t)(ty+i)*D_ + tx];
        t[ty+i][tx] = v;
        g_uw3h[((size_t)b*J_ + j0+ty+i)*D_ + d0 + tx] = __float2half(v * w3v);
    }
    __syncthreads();
    __half* Tb = g_uth + ((size_t)b*D_ + d0)*J_ + j0;
    #pragma unroll
    for (int i = 0; i < 32; i += 8) Tb[(size_t)(ty+i)*J_ + tx] = __float2half(t[tx][ty+i]);
}

// -------- K1: scores + register softmax (M=64, depth-2, coalesced epilogue) --------
__global__ __launch_bounds__(256, 2)
void scores_kernel(const float* __restrict__ H, const float* __restrict__ w,
                   float* __restrict__ out){
    extern __shared__ char smc[];
    uint32_t smb = smem_u32(smc);
    float* stg  = (float*)(smc + V_UW);              // att1 stage (post-mainloop), 64 x 132
    float* red0 = (float*)(smc + V_RED);             // [64][4]
    float* red1 = red0 + 256;                        // [64][4]
    float* ws   = (float*)(smc + V_WS);
    float* cts  = (float*)(smc + V_CTS);
    float* hrow = (float*)(smc + V_HROW);

    int tid = threadIdx.x;
    int b = blockIdx.y, t0 = blockIdx.x * 64;
    int warp = tid >> 5, lane = tid & 31;
    int wm = warp >> 2, wn = warp & 3;
    int gid = lane >> 2, tig = lane & 3;
    int hr = tid >> 2, hq = tid & 3;

    const float*  Hb  = H + (size_t)(b*T_ + t0) * D_;
    const __half* UWb = g_uw3h + (size_t)b * J_ * D_;

    if (tid < 128) cts[tid] = g_colterm[b*J_ + tid];
    #pragma unroll
    for (int i = 0; i < 4; i++) ws[tid + i*256] = w[tid + i*256];

    // prologue: prefetch UW chunks 0 and 1 (two groups in flight)
    {
        int r = tid & 127, ch = tid >> 7;
        #pragma unroll
        for (int i = 0; i < 4; i++){
            int c16 = ch*4 + i;
            cp16(smb + V_UW + SWZ8(r, c16), UWb + (size_t)r*D_ + c16*8);
        }
        CP_COMMIT;
        #pragma unroll
        for (int i = 0; i < 4; i++){
            int c16 = ch*4 + i;
            cp16(smb + V_UW + 16384 + SWZ8(r, c16), UWb + (size_t)r*D_ + 64 + c16*8);
        }
        CP_COMMIT;
    }
    float4 hreg[4];
    #pragma unroll
    for (int i = 0; i < 4; i++)
        hreg[i] = *(const float4*)(Hb + (size_t)hr*D_ + (hq + 4*i)*4);
    __syncthreads();                                 // ws/cts visible

    float hp = 0.f;
    {   // STS H chunk0 (fp16) + hrow partial
        #pragma unroll
        for (int i = 0; i < 4; i++){
            int f4 = hq + 4*i;
            float4 h = hreg[i];
            __half2 p0 = __floats2half2_rn(h.x, h.y), p1 = __floats2half2_rn(h.z, h.w);
            uint32_t a = smb + V_HH + SWZ8(hr, f4 >> 1) + (f4 & 1)*8;
            asm volatile("st.shared.v2.b32 [%0], {%1,%2};" :: "r"(a),
                         "r"(*(uint32_t*)&p0), "r"(*(uint32_t*)&p1));
            int wb = hq*4 + 16*i;
            hp += h.x*ws[wb] + h.y*ws[wb+1] + h.z*ws[wb+2] + h.w*ws[wb+3];
        }
    }

    float acc[2][4][4];
    #pragma unroll
    for (int i = 0; i < 2; i++)
        #pragma unroll
        for (int j = 0; j < 4; j++)
            #pragma unroll
            for (int k = 0; k < 4; k++) acc[i][j][k] = 0.f;

    // ---- S = H @ (U.*w3)^T, K=1024 in 16 chunks of 64, UW pipeline depth 2 ----
    for (int kci = 0; kci < 16; kci++){
        if (kci < 15){
            #pragma unroll
            for (int i = 0; i < 4; i++)
                hreg[i] = *(const float4*)(Hb + (size_t)hr*D_ + (kci+1)*64 + (hq + 4*i)*4);
        }
        if (kci < 15){ CP_WAIT1; } else { CP_WAIT0; }
        __syncthreads();
        if (kci < 14){
            uint32_t ud = smb + V_UW + ((kci+2)%3)*16384;
            int r = tid & 127, ch = tid >> 7;
            #pragma unroll
            for (int i = 0; i < 4; i++){
                int c16 = ch*4 + i;
                cp16(ud + SWZ8(r, c16), UWb + (size_t)r*D_ + (kci+2)*64 + c16*8);
            }
            CP_COMMIT;
        }
        uint32_t bH = smb + V_HH + (kci & 1)*8192;
        uint32_t bUW = smb + V_UW + (kci % 3)*16384;
        int lrow = lane & 15;
        #pragma unroll
        for (int kt = 0; kt < 4; kt++){
            int lc16 = kt*2 + (lane >> 4);
            uint32_t af[2][4], bf[2][4];
            ldm4(af[0], bH  + SWZ8(wm*32      + lrow, lc16));
            ldm4(af[1], bH  + SWZ8(wm*32 + 16 + lrow, lc16));
            ldm4(bf[0], bUW + SWZ8(wn*32      + lrow, lc16));
            ldm4(bf[1], bUW + SWZ8(wn*32 + 16 + lrow, lc16));
            #pragma unroll
            for (int mt = 0; mt < 2; mt++)
                #pragma unroll
                for (int nt = 0; nt < 4; nt++)
                    mma_f16(acc[mt][nt], af[mt], bf[nt>>1][nt&1], bf[nt>>1][(nt&1)+2]);
        }
        if (kci < 15){
            uint32_t bH2 = smb + V_HH + ((kci+1) & 1)*8192;
            #pragma unroll
            for (int i = 0; i < 4; i++){
                int f4 = hq + 4*i;
                float4 h = hreg[i];
                __half2 p0 = __floats2half2_rn(h.x, h.y), p1 = __floats2half2_rn(h.z, h.w);
                uint32_t a = bH2 + SWZ8(hr, f4 >> 1) + (f4 & 1)*8;
                asm volatile("st.shared.v2.b32 [%0], {%1,%2};" :: "r"(a),
                             "r"(*(uint32_t*)&p0), "r"(*(uint32_t*)&p1));
                int wb = (kci+1)*64 + hq*4 + 16*i;
                hp += h.x*ws[wb] + h.y*ws[wb+1] + h.z*ws[wb+2] + h.w*ws[wb+3];
            }
        }
    }
    hp += __shfl_xor_sync(0xffffffffu, hp, 1);
    hp += __shfl_xor_sync(0xffffffffu, hp, 2);
    __syncthreads();                                 // mainloop done; UW region free
    if (hq == 0) hrow[hr] = hp;

    // ---- register softmax ----
    int col0 = wn*32 + 2*tig;           // + nt*8
    #pragma unroll
    for (int mt = 0; mt < 2; mt++)
        #pragma unroll
        for (int nt = 0; nt < 4; nt++){
            acc[mt][nt][0] += cts[col0 + nt*8];
            acc[mt][nt][1] += cts[col0 + nt*8 + 1];
            acc[mt][nt][2] += cts[col0 + nt*8];
            acc[mt][nt][3] += cts[col0 + nt*8 + 1];
        }
    float rm[2][2];
    #pragma unroll
    for (int mt = 0; mt < 2; mt++)
        #pragma unroll
        for (int h = 0; h < 2; h++){
            float m = fmaxf(acc[mt][0][2*h], acc[mt][0][2*h+1]);
            #pragma unroll
            for (int nt = 1; nt < 4; nt++)
                m = fmaxf(m, fmaxf(acc[mt][nt][2*h], acc[mt][nt][2*h+1]));
            m = fmaxf(m, __shfl_xor_sync(0xffffffffu, m, 1));
            m = fmaxf(m, __shfl_xor_sync(0xffffffffu, m, 2));
            rm[mt][h] = m;
        }
    if (tig == 0){
        #pragma unroll
        for (int mt = 0; mt < 2; mt++)
            #pragma unroll
            for (int h = 0; h < 2; h++)
                red0[(wm*32 + mt*16 + h*8 + gid)*4 + wn] = rm[mt][h];
    }
    __syncthreads();
    float rs[2][2];
    #pragma unroll
    for (int mt = 0; mt < 2; mt++)
        #pragma unroll
        for (int h = 0; h < 2; h++){
            int r = wm*32 + mt*16 + h*8 + gid;
            float m = fmaxf(fmaxf(red0[r*4], red0[r*4+1]), fmaxf(red0[r*4+2], red0[r*4+3]));
            rm[mt][h] = m;
            float s = 0.f;
            #pragma unroll
            for (int nt = 0; nt < 4; nt++){
                acc[mt][nt][2*h]   = __expf(acc[mt][nt][2*h]   - m);
                acc[mt][nt][2*h+1] = __expf(acc[mt][nt][2*h+1] - m);
                s += acc[mt][nt][2*h] + acc[mt][nt][2*h+1];
            }
            s += __shfl_xor_sync(0xffffffffu, s, 1);
            s += __shfl_xor_sync(0xffffffffu, s, 2);
            rs[mt][h] = s;
        }
    if (tig == 0){
        #pragma unroll
        for (int mt = 0; mt < 2; mt++)
            #pragma unroll
            for (int h = 0; h < 2; h++)
                red1[(wm*32 + mt*16 + h*8 + gid)*4 + wn] = rs[mt][h];
    }
    __syncthreads();
    // stage normalized att1 into smem (fragment order), rowmax to global
    #pragma unroll
    for (int mt = 0; mt < 2; mt++)
        #pragma unroll
        for (int h = 0; h < 2; h++){
            int r = wm*32 + mt*16 + h*8 + gid;
            float inv = 1.f / (red1[r*4] + red1[r*4+1] + red1[r*4+2] + red1[r*4+3]);
            #pragma unroll
            for (int nt = 0; nt < 4; nt++){
                int c = col0 + nt*8;
                *(float2*)(stg + r*132 + c) =
                    make_float2(acc[mt][nt][2*h] * inv, acc[mt][nt][2*h+1] * inv);
            }
            if (wn == 0 && tig == 0)
                g_rowmax[b*T_ + t0 + r] = rm[mt][h] + hrow[r];
        }
    __syncthreads();
    // coalesced write pass: fp32 att1 (16B/thread) + fp16 att1h (8B/thread)
    float* att1out = out + (size_t)(b*T_ + t0) * J_;
    __half* a1h = g_att1h + (size_t)(b*T_ + t0) * J_;
    #pragma unroll
    for (int it = 0; it < 8; it++){
        int idx = tid + it*256;       // < 2048
        int r = idx >> 5, c4 = (idx & 31)*4;
        float4 v = *(float4*)(stg + r*132 + c4);
        *(float4*)(att1out + (size_t)r*J_ + c4) = v;
        __half2 ha = __floats2half2_rn(v.x, v.y), hb = __floats2half2_rn(v.z, v.w);
        uint2 u = make_uint2(*(uint32_t*)&ha, *(uint32_t*)&hb);
        *(uint2*)(a1h + (size_t)r*J_ + c4) = u;
    }
}

// -------- K2: att2 = softmax_t(rowmax) --------
__global__ void att2_kernel(float* __restrict__ out){
    __shared__ float red[8];
    int b = blockIdx.x, tid = threadIdx.x;
    float v[8];
    #pragma unroll
    for (int i = 0; i < 8; i++) v[i] = g_rowmax[b*T_ + tid + i*256];
    float mx = v[0];
    #pragma unroll
    for (int i = 1; i < 8; i++) mx = fmaxf(mx, v[i]);
    #pragma unroll
    for (int o = 16; o; o >>= 1) mx = fmaxf(mx, __shfl_xor_sync(0xffffffffu, mx, o));
    if ((tid & 31) == 0) red[tid >> 5] = mx;
    __syncthreads();
    mx = red[0];
    #pragma unroll
    for (int i = 1; i < 8; i++) mx = fmaxf(mx, red[i]);
    float e[8], s = 0.f;
    #pragma unroll
    for (int i = 0; i < 8; i++){ e[i] = __expf(v[i] - mx); s += e[i]; }
    #pragma unroll
    for (int o = 16; o; o >>= 1) s += __shfl_xor_sync(0xffffffffu, s, o);
    __syncthreads();
    if ((tid & 31) == 0) red[tid >> 5] = s;
    __syncthreads();
    s = 0.f;
    #pragma unroll
    for (int i = 0; i < 8; i++) s += red[i];
    float inv = 1.f / s;
    #pragma unroll
    for (int i = 0; i < 8; i++) out[OFF_ATT2 + b*T_ + tid + i*256] = e[i] * inv;
}

// -------- K3a: partial agg2 --------
__global__ __launch_bounds__(128)
void agg2p_kernel(const float* __restrict__ H, const float* __restrict__ out){
    int b  = blockIdx.z;
    int tc = blockIdx.y;
    int d4 = blockIdx.x * 128 + threadIdx.x;
    int t0 = tc * (T_/TCH);
    const float* a2 = out + OFF_ATT2 + b*T_ + t0;
    const float4* Hb = (const float4*)(H + ((size_t)b*T_ + t0) * D_) + d4;
    float4 acc = make_float4(0.f, 0.f, 0.f, 0.f);
    #pragma unroll 1
    for (int t = 0; t < T_/TCH; t += 8){
        #pragma unroll
        for (int u = 0; u < 8; u++){
            float a = a2[t+u];
            float4 h = Hb[(size_t)(t+u) * 256];
            acc.x += a*h.x; acc.y += a*h.y; acc.z += a*h.z; acc.w += a*h.w;
        }
    }
    ((float4*)g_agg2p)[((size_t)b*TCH + tc)*256 + d4] = acc;
}

// -------- K3b: reduce --------
__global__ void agg2r_kernel(){
    int idx = blockIdx.x * 256 + threadIdx.x;
    int b = idx >> 10, d = idx & 1023;
    const float* p = g_agg2p + (size_t)b*TCH*D_ + d;
    float acc = 0.f;
    #pragma unroll
    for (int c = 0; c < TCH; c++) acc += p[(size_t)c*D_];
    g_agg2[idx] = acc;
}

// -------- K1b: agg1 = att1 @ U + full G epilogue (G1..G4) --------
__global__ __launch_bounds__(256, 3)
void agg1g_kernel(const float* __restrict__ H, float* __restrict__ out){
    extern __shared__ char smc[];
    uint32_t smb = smem_u32(smc);
    float* stage = (float*)smc;      // 128 x 68 fp32, overlays A/B after mma
    int tid = threadIdx.x;
    int b  = blockIdx.z;
    int m0 = blockIdx.y * 128;       // t rows
    int n0 = blockIdx.x * 64;        // d cols
    int warp = tid >> 5, lane = tid & 31;
    int wm = warp >> 1, wn = warp & 1;
    int gid = lane >> 2, tig = lane & 3;

    const __half* Ab = g_att1h + (size_t)(b*T_ + m0) * J_;
    const __half* Bb = g_uth + ((size_t)b*D_ + n0) * J_;

    #pragma unroll
    for (int i = 0; i < 8; i++){
        int idx = tid + i*256;       // < 2048
        int r = idx >> 4, c = idx & 15;
        cp16(smb + SWZ16(r, c), Ab + (size_t)r*J_ + c*8);
    }
    #pragma unroll
    for (int i = 0; i < 4; i++){
        int idx = tid + i*256;       // < 1024
        int r = idx >> 4, c = idx & 15;
        cp16(smb + 32768 + SWZ16(r, c), Bb + (size_t)r*J_ + c*8);
    }
    CP_COMMIT;

    float acc[2][4][4];
    #pragma unroll
    for (int i = 0; i < 2; i++)
        #pragma unroll
        for (int j = 0; j < 4; j++)
            #pragma unroll
            for (int k = 0; k < 4; k++) acc[i][j][k] = 0.f;

    CP_WAIT0;
    __syncthreads();

    int lrow = lane & 15;
    uint32_t aB = smb, bB = smb + 32768;
    #pragma unroll
    for (int kt = 0; kt < 8; kt++){
        int lc16 = kt*2 + (lane >> 4);
        uint32_t af[2][4], bf[2][4];
        ldm4(af[0], aB + SWZ16(wm*32      + lrow, lc16));
        ldm4(af[1], aB + SWZ16(wm*32 + 16 + lrow, lc16));
        ldm4(bf[0], bB + SWZ16(wn*32      + lrow, lc16));
        ldm4(bf[1], bB + SWZ16(wn*32 + 16 + lrow, lc16));
        #pragma unroll
        for (int mt = 0; mt < 2; mt++)
            #pragma unroll
            for (int nt = 0; nt < 4; nt++)
                mma_f16(acc[mt][nt], af[mt], bf[nt>>1][nt&1], bf[nt>>1][(nt&1)+2]);
    }
    __syncthreads();

    #pragma unroll
    for (int mt = 0; mt < 2; mt++)
        #pragma unroll
        for (int nt = 0; nt < 4; nt++){
            int r0 = wm*32 + mt*16 + gid;
            int c  = wn*32 + nt*8 + 2*tig;
            *(float2*)(stage + r0*68 + c)     = make_float2(acc[mt][nt][0], acc[mt][nt][1]);
            *(float2*)(stage + (r0+8)*68 + c) = make_float2(acc[mt][nt][2], acc[mt][nt][3]);
        }
    __syncthreads();

    const float* Hb = H + (size_t)(b*T_ + m0) * D_ + n0;
    const float* A2 = g_agg2 + b*D_ + n0;
    float* Gb = out + OFF_G + (size_t)(b*T_ + m0) * 4096 + n0;
    #pragma unroll
    for (int it = 0; it < 8; it++){
        int idx = tid + it*256;       // < 2048
        int r = idx >> 4, c4 = (idx & 15)*4;
        float4 a1 = *(float4*)(stage + r*68 + c4);
        float4 h  = *(const float4*)(Hb + (size_t)r*D_ + c4);
        float4 a2 = *(const float4*)(A2 + c4);
        float* g = Gb + (size_t)r*4096 + c4;
        *(float4*)(g)        = h;
        *(float4*)(g + 1024) = a1;
        *(float4*)(g + 2048) = make_float4(a1.x*h.x, a1.y*h.y, a1.z*h.z, a1.w*h.w);
        *(float4*)(g + 3072) = make_float4(h.x*a2.x, h.y*a2.y, h.z*a2.z, h.w*a2.w);
    }
}

extern "C" void kernel_launch(void* const* d_in, const int* in_sizes, int n_in,
                              void* d_out, int out_size){
    const float* H    = (const float*)d_in[0];
    const float* U    = (const float*)d_in[1];
    const float* w    = (const float*)d_in[2];
    const float* bias = (const float*)d_in[3];
    float* out = (float*)d_out;

    cudaFuncSetAttribute(scores_kernel, cudaFuncAttributeMaxDynamicSharedMemorySize, V_TOT);
    cudaFuncSetAttribute(agg1g_kernel, cudaFuncAttributeMaxDynamicSharedMemorySize, 49152);

    colterm_kernel<<<256, 256>>>(U, w, bias);
    uwt_kernel<<<dim3(D_/32, J_/32, B_), dim3(32, 8)>>>(U, w);
    scores_kernel<<<dim3(T_/64, B_), 256, V_TOT>>>(H, w, out);
    att2_kernel<<<B_, 256>>>(out);
    agg2p_kernel<<<dim3(2, TCH, B_), 128>>>(H, out);
    agg2r_kernel<<<B_*D_/256, 256>>>();
    agg1g_kernel<<<dim3(D_/64, T_/128, B_), 256, 49152>>>(H, out);
}